// round 7
// baseline (speedup 1.0000x reference)
#include <cuda_runtime.h>
#include <cuda_fp16.h>
#include <cstdint>

// ============================================================================
// NestedMoEModel: softmax gate row-sums to 1 => gate path is a no-op.
// out[B, G*H] = x @ (sum_e W_exp)^T + sum_e b_exp
// Single GEMM M=32768, N=2048, K=256 via fp16 mma.sync (fp32 accumulate).
// PTX target is sm_103 (no 'a') -> tcgen05 unavailable; mma.sync path.
// R7: persistent CTAs (grid = 2*SMs), flat chunk pipeline crossing tile
//     boundaries (one prologue stall per CTA instead of one per tile),
//     epilogue overlapped with next tile's prefetch, bias via __ldg.
// ============================================================================

#define DINLINE __device__ __forceinline__

static constexpr int Bsz = 32768;
static constexpr int Dsz = 256;     // K
static constexpr int NN  = 2048;    // G*H = output cols
static constexpr int M_TILE = 128;
static constexpr int N_TILE = 128;
static constexpr int K_CHUNK = 64;                   // halves per chunk (128B rows)
static constexpr int NUM_CHUNKS = Dsz / K_CHUNK;     // 4
static constexpr int STAGES = 3;
static constexpr int THREADS = 128;                  // 4 warps, 2x2 grid of 64x64
static constexpr int N_TILES_TOTAL = (Bsz / M_TILE) * (NN / N_TILE);  // 4096

// SMEM: 3 stages, each A(16KB)+B(16KB)
static constexpr int A_BYTES = M_TILE * 128;         // 16384
static constexpr int B_BYTES = N_TILE * 128;         // 16384
static constexpr int STAGE_BYTES = A_BYTES + B_BYTES;    // 32768
static constexpr int SMEM_TOTAL = STAGES * STAGE_BYTES;  // 98304 -> 2 CTAs/SM

// Scratch (device globals: no allocations allowed)
__device__ __align__(128) __half g_Wh[NN * Dsz];     // 1MB  fp16 reduced weights
__device__ __align__(128) __half g_Xh[Bsz * Dsz];    // 16MB fp16 x
__device__ __align__(128) float  g_bsum[NN];

// ---------------------------------------------------------------------------
// helpers
// ---------------------------------------------------------------------------
DINLINE uint32_t smem_u32(const void* p) {
    uint32_t a;
    asm("{ .reg .u64 t; cvta.to.shared.u64 t, %1; cvt.u32.u64 %0, t; }"
        : "=r"(a) : "l"(p));
    return a;
}

DINLINE void cp_async16(uint32_t saddr, const void* gaddr) {
    asm volatile("cp.async.cg.shared.global [%0], [%1], 16;"
                 :: "r"(saddr), "l"(gaddr) : "memory");
}
#define CP_COMMIT() asm volatile("cp.async.commit_group;" ::: "memory")
#define CP_WAIT(n)  asm volatile("cp.async.wait_group %0;" :: "n"(n) : "memory")

// SW128-style XOR swizzle for 128B rows (16B granularity)
#define SWZ(o) ((o) ^ (((o) >> 3) & 0x70))

DINLINE void ldsm_x4(uint32_t& r0, uint32_t& r1, uint32_t& r2, uint32_t& r3,
                     uint32_t addr) {
    asm volatile("ldmatrix.sync.aligned.m8n8.x4.shared.b16 {%0,%1,%2,%3}, [%4];"
                 : "=r"(r0), "=r"(r1), "=r"(r2), "=r"(r3) : "r"(addr));
}

DINLINE void mma16816(float* d, const uint32_t* a, const uint32_t* b) {
    asm volatile(
        "mma.sync.aligned.m16n8k16.row.col.f32.f16.f16.f32 "
        "{%0,%1,%2,%3}, {%4,%5,%6,%7}, {%8,%9}, {%0,%1,%2,%3};"
        : "+f"(d[0]), "+f"(d[1]), "+f"(d[2]), "+f"(d[3])
        : "r"(a[0]), "r"(a[1]), "r"(a[2]), "r"(a[3]), "r"(b[0]), "r"(b[1]));
}

// ---------------------------------------------------------------------------
// Fused prep: blocks [0,2048): W reduce over experts -> fp16 + bias sum.
//             blocks [2048,10240): x -> fp16 (4 floats/thread).
// ---------------------------------------------------------------------------
__global__ void __launch_bounds__(256)
prep_kernel(const float* __restrict__ X,
            const float* __restrict__ W_exp,
            const float* __restrict__ b_exp) {
    const int blk = blockIdx.x;
    if (blk < NN) {
        const int n = blk;                 // g*256 + h
        const int i = threadIdx.x;         // k index
        const int g = n >> 8, h = n & 255;
        const float* base = W_exp + (size_t)(g * 8) * 65536 + (size_t)h * 256 + i;
        float s = 0.f;
#pragma unroll
        for (int e = 0; e < 8; e++) s += base[(size_t)e * 65536];
        g_Wh[(size_t)n * 256 + i] = __float2half_rn(s);
        if (i == 0) {
            float bs = 0.f;
#pragma unroll
            for (int e = 0; e < 8; e++) bs += b_exp[(g * 8 + e) * 256 + h];
            g_bsum[n] = bs;
        }
    } else {
        const size_t idx = (((size_t)(blk - NN) * 256) + threadIdx.x) * 4;
        float4 v = *(const float4*)(X + idx);
        __half2 lo = __floats2half2_rn(v.x, v.y);
        __half2 hi = __floats2half2_rn(v.z, v.w);
        uint2 pk;
        pk.x = *(uint32_t*)&lo;
        pk.y = *(uint32_t*)&hi;
        *(uint2*)(g_Xh + idx) = pk;
    }
}
static constexpr int PREP_BLOCKS = NN + (Bsz * Dsz) / (256 * 4);   // 10240

// ---------------------------------------------------------------------------
// chunk loads: A 1024 16B-chunks + B 1024 -> 8+8 per thread (128 threads)
// ---------------------------------------------------------------------------
DINLINE void load_chunk(uint32_t stage_base, int m_base, int n_base,
                        int kc, int tid) {
    const uint32_t astage = stage_base;
    const uint32_t bstage = stage_base + A_BYTES;
#pragma unroll
    for (int i = 0; i < 8; i++) {
        const int idx = i * THREADS + tid;  // [0, 1024)
        const int row = idx >> 3;
        const int c16 = idx & 7;
        const __half* g = g_Xh + (size_t)(m_base + row) * 256
                          + kc * K_CHUNK + c16 * 8;
        cp_async16(astage + SWZ(row * 128 + c16 * 16), g);
    }
#pragma unroll
    for (int i = 0; i < 8; i++) {
        const int idx = i * THREADS + tid;
        const int row = idx >> 3;
        const int c16 = idx & 7;
        const __half* g = g_Wh + (size_t)(n_base + row) * 256
                          + kc * K_CHUNK + c16 * 8;
        cp_async16(bstage + SWZ(row * 128 + c16 * 16), g);
    }
    CP_COMMIT();
}

// load all fragments for one k16 step into (a, b)
DINLINE void load_frags(uint32_t astage, uint32_t bstage,
                        int m_off, int n_off, int grp, int r8, int ks,
                        uint32_t a[4][4], uint32_t b[8][2]) {
#pragma unroll
    for (int mi = 0; mi < 4; mi++) {
        const int row = m_off + mi * 16 + (grp & 1) * 8 + r8;
        const int cg  = ks * 2 + (grp >> 1);
        ldsm_x4(a[mi][0], a[mi][1], a[mi][2], a[mi][3],
                astage + SWZ(row * 128 + cg * 16));
    }
#pragma unroll
    for (int p = 0; p < 4; p++) {
        const int row = n_off + p * 16 + (grp >> 1) * 8 + r8;
        const int cg  = ks * 2 + (grp & 1);
        ldsm_x4(b[2 * p][0], b[2 * p][1], b[2 * p + 1][0], b[2 * p + 1][1],
                bstage + SWZ(row * 128 + cg * 16));
    }
}

// ---------------------------------------------------------------------------
// GEMM: out = Xh @ Wh^T + bsum
// Persistent CTAs: each CTA iterates tiles t = bid + j*gridDim.
// Flat chunk pipeline over (tile, kc) iterations, 3-stage cp.async ring.
// CTA 128x128, 128 threads (4 warps, 2x2 grid, warp tile 64x64). 2 CTAs/SM.
// ---------------------------------------------------------------------------
__global__ void __launch_bounds__(THREADS, 2)
gemm_kernel(float* __restrict__ out) {
    extern __shared__ char smem[];
    const uint32_t sbase = smem_u32(smem);
    const int tid = threadIdx.x;
    const int wid = tid >> 5;
    const int lid = tid & 31;
    const int bid = blockIdx.x;
    const int grid = gridDim.x;

    const int n_my_tiles = (N_TILES_TOTAL - bid + grid - 1) / grid;
    const int total = n_my_tiles * NUM_CHUNKS;      // chunk iterations

    // warp tiling: 2 (m) x 2 (n) warps, warp tile 64x64
    const int warp_m = wid >> 1;
    const int warp_n = wid & 1;
    const int m_off = warp_m * 64;
    const int n_off = warp_n * 64;
    const int grp = lid >> 3;                   // 0..3
    const int r8  = lid & 7;

    // iteration i -> tile bid + (i>>2)*grid, chunk i&3, stage i%3
    // tile t: mtile = t>>4 (A reuse across 16 consecutive t), ntile = t&15
    auto issue_load = [&](int i) {
        const int t  = bid + (i >> 2) * grid;
        const int kc = i & 3;
        const int mb = (t >> 4) * M_TILE;
        const int nb = (t & 15) * N_TILE;
        load_chunk(sbase + (i % 3) * STAGE_BYTES, mb, nb, kc, tid);
    };

    // prologue: 2 iterations in flight
    issue_load(0);
    issue_load(1);

    float acc[4][8][4];
#pragma unroll
    for (int mi = 0; mi < 4; mi++)
#pragma unroll
        for (int ni = 0; ni < 8; ni++)
#pragma unroll
            for (int j = 0; j < 4; j++) acc[mi][ni][j] = 0.f;

    uint32_t abuf[2][4][4];
    uint32_t bbuf[2][8][2];

    for (int i = 0; i < total; i++) {
        // group for iteration i complete (one group, i+1, stays in flight)
        CP_WAIT(1);
        __syncthreads();

        // prefetch iteration i+2 (writes stage (i+2)%3 == (i-1)%3, whose
        // compute finished before the sync above). Empty commit keeps the
        // group count uniform at the tail.
        if (i + 2 < total) issue_load(i + 2);
        else CP_COMMIT();

        const uint32_t astage = sbase + (i % 3) * STAGE_BYTES;
        const uint32_t bstage = astage + A_BYTES;

        // prime k-step 0, then double-buffered fragments
        load_frags(astage, bstage, m_off, n_off, grp, r8, 0, abuf[0], bbuf[0]);
#pragma unroll
        for (int ks = 0; ks < 4; ks++) {
            const int cur = ks & 1, nxt = cur ^ 1;
            if (ks < 3)
                load_frags(astage, bstage, m_off, n_off, grp, r8, ks + 1,
                           abuf[nxt], bbuf[nxt]);
#pragma unroll
            for (int mi = 0; mi < 4; mi++)
#pragma unroll
                for (int ni = 0; ni < 8; ni++)
                    mma16816(acc[mi][ni], abuf[cur][mi], bbuf[cur][ni]);
        }

        // tile finished -> epilogue (overlaps next tile's in-flight loads)
        if ((i & 3) == 3) {
            const int t = bid + (i >> 2) * grid;
            const int m_base = (t >> 4) * M_TILE;
            const int n_base = (t & 15) * N_TILE;
            const int qrow = lid >> 2;
            const int qcol = (lid & 3) * 2;
#pragma unroll
            for (int mi = 0; mi < 4; mi++) {
                const int r0 = m_base + m_off + mi * 16 + qrow;
                float* orow0 = out + (size_t)r0 * NN + n_base;
                float* orow1 = orow0 + (size_t)8 * NN;
#pragma unroll
                for (int ni = 0; ni < 8; ni++) {
                    const int col = n_off + ni * 8 + qcol;
                    const float2 bv = __ldg((const float2*)(g_bsum + n_base + col));
                    float2 v0 = make_float2(acc[mi][ni][0] + bv.x,
                                            acc[mi][ni][1] + bv.y);
                    float2 v1 = make_float2(acc[mi][ni][2] + bv.x,
                                            acc[mi][ni][3] + bv.y);
                    *(float2*)(orow0 + col) = v0;
                    *(float2*)(orow1 + col) = v1;
#pragma unroll
                    for (int j = 0; j < 4; j++) acc[mi][ni][j] = 0.f;
                }
            }
        }
    }
}

// ---------------------------------------------------------------------------
// Launch
// ---------------------------------------------------------------------------
extern "C" void kernel_launch(void* const* d_in, const int* in_sizes, int n_in,
                              void* d_out, int out_size) {
    const float* x     = (const float*)d_in[0];
    // d_in[1]=W_gate, d_in[2]=b_gate: softmax row-sum == 1 -> unused.
    const float* W_exp = (const float*)d_in[3];
    const float* b_exp = (const float*)d_in[4];
    float* out = (float*)d_out;

    int nsm = 148;
    cudaDeviceGetAttribute(&nsm, cudaDevAttrMultiProcessorCount, 0);

    cudaFuncSetAttribute(gemm_kernel,
                         cudaFuncAttributeMaxDynamicSharedMemorySize, SMEM_TOTAL);

    prep_kernel<<<PREP_BLOCKS, 256>>>(x, W_exp, b_exp);
    gemm_kernel<<<2 * nsm, THREADS, SMEM_TOTAL>>>(out);
}

// round 8
// speedup vs baseline: 1.0185x; 1.0185x over previous
#include <cuda_runtime.h>
#include <cuda_fp16.h>
#include <cstdint>

// ============================================================================
// NestedMoEModel: softmax gate row-sums to 1 => gate path is a no-op.
// out[B, G*H] = x @ (sum_e W_exp)^T + sum_e b_exp
// Single GEMM M=32768, N=2048, K=256 via fp16 mma.sync (fp32 accumulate).
// PTX target is sm_103 (no 'a') -> tcgen05 unavailable; mma.sync path.
// R8: R6 base (4096 CTAs, 128 thr, 64x64 warp tiles, 2 CTAs/SM) +
//     chunk-boundary sync moved before ks3 MMAs (prime-LDSM hidden under
//     MMAs, refill folded -> 1 sync/chunk) + prep xconv MLP 1->4.
// ============================================================================

#define DINLINE __device__ __forceinline__

static constexpr int Bsz = 32768;
static constexpr int Dsz = 256;     // K
static constexpr int NN  = 2048;    // G*H = output cols
static constexpr int M_TILE = 128;
static constexpr int N_TILE = 128;
static constexpr int K_CHUNK = 64;                   // halves per chunk (128B rows)
static constexpr int NUM_CHUNKS = Dsz / K_CHUNK;     // 4
static constexpr int STAGES = 3;
static constexpr int THREADS = 128;                  // 4 warps, 2x2 grid of 64x64

// SMEM: 3 stages, each A(16KB)+B(16KB), + bias
static constexpr int A_BYTES = M_TILE * 128;         // 16384
static constexpr int B_BYTES = N_TILE * 128;         // 16384
static constexpr int STAGE_BYTES = A_BYTES + B_BYTES;    // 32768
static constexpr int OFF_BIAS = STAGES * STAGE_BYTES;    // 98304
static constexpr int SMEM_TOTAL = OFF_BIAS + N_TILE * 4; // 98816 -> 2 CTAs/SM

// Scratch (device globals: no allocations allowed)
__device__ __align__(128) __half g_Wh[NN * Dsz];     // 1MB  fp16 reduced weights
__device__ __align__(128) __half g_Xh[Bsz * Dsz];    // 16MB fp16 x
__device__ __align__(128) float  g_bsum[NN];

// ---------------------------------------------------------------------------
// helpers
// ---------------------------------------------------------------------------
DINLINE uint32_t smem_u32(const void* p) {
    uint32_t a;
    asm("{ .reg .u64 t; cvta.to.shared.u64 t, %1; cvt.u32.u64 %0, t; }"
        : "=r"(a) : "l"(p));
    return a;
}

DINLINE void cp_async16(uint32_t saddr, const void* gaddr) {
    asm volatile("cp.async.cg.shared.global [%0], [%1], 16;"
                 :: "r"(saddr), "l"(gaddr) : "memory");
}
#define CP_COMMIT() asm volatile("cp.async.commit_group;" ::: "memory")
#define CP_WAIT(n)  asm volatile("cp.async.wait_group %0;" :: "n"(n) : "memory")

// SW128-style XOR swizzle for 128B rows (16B granularity)
#define SWZ(o) ((o) ^ (((o) >> 3) & 0x70))

DINLINE void ldsm_x4(uint32_t& r0, uint32_t& r1, uint32_t& r2, uint32_t& r3,
                     uint32_t addr) {
    asm volatile("ldmatrix.sync.aligned.m8n8.x4.shared.b16 {%0,%1,%2,%3}, [%4];"
                 : "=r"(r0), "=r"(r1), "=r"(r2), "=r"(r3) : "r"(addr));
}

DINLINE void mma16816(float* d, const uint32_t* a, const uint32_t* b) {
    asm volatile(
        "mma.sync.aligned.m16n8k16.row.col.f32.f16.f16.f32 "
        "{%0,%1,%2,%3}, {%4,%5,%6,%7}, {%8,%9}, {%0,%1,%2,%3};"
        : "+f"(d[0]), "+f"(d[1]), "+f"(d[2]), "+f"(d[3])
        : "r"(a[0]), "r"(a[1]), "r"(a[2]), "r"(a[3]), "r"(b[0]), "r"(b[1]));
}

// ---------------------------------------------------------------------------
// Fused prep: blocks [0,2048): W reduce over experts -> fp16 + bias sum.
//             blocks [2048,4096): x -> fp16, 4 independent float4 per thread.
// ---------------------------------------------------------------------------
__global__ void __launch_bounds__(256)
prep_kernel(const float* __restrict__ X,
            const float* __restrict__ W_exp,
            const float* __restrict__ b_exp) {
    const int blk = blockIdx.x;
    if (blk < NN) {
        const int n = blk;                 // g*256 + h
        const int i = threadIdx.x;         // k index
        const int g = n >> 8, h = n & 255;
        const float* base = W_exp + (size_t)(g * 8) * 65536 + (size_t)h * 256 + i;
        float s = 0.f;
#pragma unroll
        for (int e = 0; e < 8; e++) s += base[(size_t)e * 65536];
        g_Wh[(size_t)n * 256 + i] = __float2half_rn(s);
        if (i == 0) {
            float bs = 0.f;
#pragma unroll
            for (int e = 0; e < 8; e++) bs += b_exp[(g * 8 + e) * 256 + h];
            g_bsum[n] = bs;
        }
    } else {
        // each block: 256 threads x 4 float4 = 4096 floats (MLP = 4)
        const size_t f4base = (size_t)(blk - NN) * 1024 + threadIdx.x;
        const float4* src = (const float4*)X;
        float4 v[4];
#pragma unroll
        for (int j = 0; j < 4; j++) v[j] = src[f4base + j * 256];
#pragma unroll
        for (int j = 0; j < 4; j++) {
            __half2 lo = __floats2half2_rn(v[j].x, v[j].y);
            __half2 hi = __floats2half2_rn(v[j].z, v[j].w);
            uint2 pk;
            pk.x = *(uint32_t*)&lo;
            pk.y = *(uint32_t*)&hi;
            *(uint2*)(g_Xh + (f4base + j * 256) * 4) = pk;
        }
    }
}
static constexpr int PREP_BLOCKS = NN + (Bsz * Dsz) / (256 * 16);   // 4096

// ---------------------------------------------------------------------------
// chunk loads: A 1024 16B-chunks + B 1024 -> 8+8 per thread (128 threads)
// ---------------------------------------------------------------------------
DINLINE void load_chunk(uint32_t stage_base, int m_base, int n_base,
                        int kc, int tid) {
    const uint32_t astage = stage_base;
    const uint32_t bstage = stage_base + A_BYTES;
#pragma unroll
    for (int i = 0; i < 8; i++) {
        const int idx = i * THREADS + tid;  // [0, 1024)
        const int row = idx >> 3;
        const int c16 = idx & 7;
        const __half* g = g_Xh + (size_t)(m_base + row) * 256
                          + kc * K_CHUNK + c16 * 8;
        cp_async16(astage + SWZ(row * 128 + c16 * 16), g);
    }
#pragma unroll
    for (int i = 0; i < 8; i++) {
        const int idx = i * THREADS + tid;
        const int row = idx >> 3;
        const int c16 = idx & 7;
        const __half* g = g_Wh + (size_t)(n_base + row) * 256
                          + kc * K_CHUNK + c16 * 8;
        cp_async16(bstage + SWZ(row * 128 + c16 * 16), g);
    }
    CP_COMMIT();
}

// load all fragments for one k16 step into (a, b)
DINLINE void load_frags(uint32_t astage, uint32_t bstage,
                        int m_off, int n_off, int grp, int r8, int ks,
                        uint32_t a[4][4], uint32_t b[8][2]) {
#pragma unroll
    for (int mi = 0; mi < 4; mi++) {
        const int row = m_off + mi * 16 + (grp & 1) * 8 + r8;
        const int cg  = ks * 2 + (grp >> 1);
        ldsm_x4(a[mi][0], a[mi][1], a[mi][2], a[mi][3],
                astage + SWZ(row * 128 + cg * 16));
    }
#pragma unroll
    for (int p = 0; p < 4; p++) {
        const int row = n_off + p * 16 + (grp >> 1) * 8 + r8;
        const int cg  = ks * 2 + (grp & 1);
        ldsm_x4(b[2 * p][0], b[2 * p][1], b[2 * p + 1][0], b[2 * p + 1][1],
                bstage + SWZ(row * 128 + cg * 16));
    }
}

DINLINE void mma_all(float acc[4][8][4], uint32_t a[4][4], uint32_t b[8][2]) {
#pragma unroll
    for (int mi = 0; mi < 4; mi++)
#pragma unroll
        for (int ni = 0; ni < 8; ni++)
            mma16816(acc[mi][ni], a[mi], b[ni]);
}

// ---------------------------------------------------------------------------
// GEMM: out = Xh @ Wh^T + bsum
// CTA 128x128, 128 threads (4 warps, 2x2 grid, warp tile 64x64). 2 CTAs/SM.
// 3-stage cp.async ring; boundary sync moved before ks3 MMAs so the next
// chunk's fragment priming hides under them.
// ---------------------------------------------------------------------------
__global__ void __launch_bounds__(THREADS, 2)
gemm_kernel(float* __restrict__ out) {
    extern __shared__ char smem[];
    const uint32_t sbase = smem_u32(smem);
    const int tid = threadIdx.x;
    const int wid = tid >> 5;
    const int lid = tid & 31;

    // 16 consecutive CTAs share one A tile (L2 locality on A)
    const int mtile = blockIdx.x >> 4;          // 0..255
    const int ntile = blockIdx.x & 15;          // 0..15
    const int m_base = mtile * M_TILE;
    const int n_base = ntile * N_TILE;

    // bias slice (visible to epilogue via the in-loop barriers)
    *(float*)(smem + OFF_BIAS + tid * 4) = g_bsum[n_base + tid];

    // ---- prologue: fill 3 stages ----
    load_chunk(sbase + 0 * STAGE_BYTES, m_base, n_base, 0, tid);
    load_chunk(sbase + 1 * STAGE_BYTES, m_base, n_base, 1, tid);
    load_chunk(sbase + 2 * STAGE_BYTES, m_base, n_base, 2, tid);

    // warp tiling: 2 (m) x 2 (n) warps, warp tile 64x64
    const int warp_m = wid >> 1;
    const int warp_n = wid & 1;
    const int m_off = warp_m * 64;
    const int n_off = warp_n * 64;
    const int grp = lid >> 3;                   // 0..3
    const int r8  = lid & 7;

    float acc[4][8][4];
#pragma unroll
    for (int mi = 0; mi < 4; mi++)
#pragma unroll
        for (int ni = 0; ni < 8; ni++)
#pragma unroll
            for (int j = 0; j < 4; j++) acc[mi][ni][j] = 0.f;

    uint32_t abuf[2][4][4];
    uint32_t bbuf[2][8][2];

    // chunk 0 ready
    CP_WAIT(2);
    __syncthreads();
    load_frags(sbase, sbase + A_BYTES, m_off, n_off, grp, r8, 0,
               abuf[0], bbuf[0]);

    // ---- main loop over K chunks; each chunk enters with buf0 = its ks0 ----
#pragma unroll
    for (int kc = 0; kc < NUM_CHUNKS; kc++) {
        const uint32_t astage = sbase + (kc % 3) * STAGE_BYTES;
        const uint32_t bstage = astage + A_BYTES;

        // ks 0..2: prefetch ks+1 frags, run MMAs on current frags
#pragma unroll
        for (int ks = 0; ks < 3; ks++) {
            const int cur = ks & 1, nxt = cur ^ 1;
            load_frags(astage, bstage, m_off, n_off, grp, r8, ks + 1,
                       abuf[nxt], bbuf[nxt]);
            mma_all(acc, abuf[cur], bbuf[cur]);
        }

        // ks 3: nothing reads this stage anymore (frags already in regs).
        // Boundary: wait next chunk's group, sync, (refill), prime next ks0;
        // all of it issues BEFORE the ks3 MMAs so prime latency hides.
        if (kc == 0) {
            CP_WAIT(1);
            __syncthreads();
            load_chunk(sbase + 0 * STAGE_BYTES, m_base, n_base, 3, tid);
            const uint32_t na = sbase + 1 * STAGE_BYTES;
            load_frags(na, na + A_BYTES, m_off, n_off, grp, r8, 0,
                       abuf[0], bbuf[0]);
        } else if (kc == 1) {
            CP_WAIT(1);
            __syncthreads();
            const uint32_t na = sbase + 2 * STAGE_BYTES;
            load_frags(na, na + A_BYTES, m_off, n_off, grp, r8, 0,
                       abuf[0], bbuf[0]);
        } else if (kc == 2) {
            CP_WAIT(0);
            __syncthreads();
            const uint32_t na = sbase + 0 * STAGE_BYTES;
            load_frags(na, na + A_BYTES, m_off, n_off, grp, r8, 0,
                       abuf[0], bbuf[0]);
        }
        mma_all(acc, abuf[1], bbuf[1]);
    }

    // ---- epilogue: bias + store (float2, 32B sector-complete per lane quad) ----
    const float* sbias = (const float*)(smem + OFF_BIAS);
    const int qrow = lid >> 2;                  // 0..7
    const int qcol = (lid & 3) * 2;             // 0,2,4,6

#pragma unroll
    for (int mi = 0; mi < 4; mi++) {
        const int r0 = m_base + m_off + mi * 16 + qrow;
        float* orow0 = out + (size_t)r0 * NN + n_base;
        float* orow1 = orow0 + (size_t)8 * NN;
#pragma unroll
        for (int ni = 0; ni < 8; ni++) {
            const int col = n_off + ni * 8 + qcol;
            const float b0 = sbias[col], b1 = sbias[col + 1];
            float2 v0 = make_float2(acc[mi][ni][0] + b0, acc[mi][ni][1] + b1);
            float2 v1 = make_float2(acc[mi][ni][2] + b0, acc[mi][ni][3] + b1);
            *(float2*)(orow0 + col) = v0;
            *(float2*)(orow1 + col) = v1;
        }
    }
}

// ---------------------------------------------------------------------------
// Launch
// ---------------------------------------------------------------------------
extern "C" void kernel_launch(void* const* d_in, const int* in_sizes, int n_in,
                              void* d_out, int out_size) {
    const float* x     = (const float*)d_in[0];
    // d_in[1]=W_gate, d_in[2]=b_gate: softmax row-sum == 1 -> unused.
    const float* W_exp = (const float*)d_in[3];
    const float* b_exp = (const float*)d_in[4];
    float* out = (float*)d_out;

    cudaFuncSetAttribute(gemm_kernel,
                         cudaFuncAttributeMaxDynamicSharedMemorySize, SMEM_TOTAL);

    prep_kernel<<<PREP_BLOCKS, 256>>>(x, W_exp, b_exp);
    gemm_kernel<<<(Bsz / M_TILE) * (NN / N_TILE), THREADS, SMEM_TOTAL>>>(out);
}